// round 14
// baseline (speedup 1.0000x reference)
#include <cuda_runtime.h>
#include <cuda_bf16.h>
#include <cstdint>

#define HIDDEN 128
#define MAX_NODES 50048
#define MAX_EDGES 800000

// ---------------- scratch (static device globals; no allocation) -------------
__device__ float    g_agg[(size_t)MAX_NODES * HIDDEN];
__device__ float    g_colsum[HIDDEN];
__device__ float    g_b1eff[HIDDEN];
__device__ uint32_t g_W1t[8 * 4096];
__device__ uint32_t g_W2t[4 * 4096];

__device__ __forceinline__ uint32_t f2tf32(float f) {
    uint32_t u;
    asm("cvt.rna.tf32.f32 %0, %1;" : "=r"(u) : "f"(f));
    return u;
}

// ---------------- kernel 1: fused init (zero agg+colsum, wconv W1/W2) --------
__global__ void __launch_bounds__(256)
init_kernel(const float* __restrict__ W1, const float* __restrict__ W2,
            int n_nodes) {
    int b   = blockIdx.x;
    int tid = threadIdx.x;
    if (b < 12) {
        const float* W = (b < 8) ? W1 : W2;
        uint32_t*    o = (b < 8) ? g_W1t : g_W2t;
        int t = (b < 8) ? b : b - 8;
        #pragma unroll
        for (int j = 0; j < 16; j++) {
            int oo = j * 256 + tid;
            int n  = oo >> 5;
            int pk = oo & 31;
            int k  = (pk & 7) * 4 + (pk >> 3);
            o[t * 4096 + oo] =
                f2tf32(__ldg(&W[(size_t)(t * 32 + k) * HIDDEN + n]));
        }
        if (b == 0 && tid < HIDDEN) g_colsum[tid] = 0.0f;
    } else {
        size_t total4 = (size_t)n_nodes * (HIDDEN / 4);
        size_t i      = (size_t)(b - 12) * 256 + tid;
        size_t stride = (size_t)(gridDim.x - 12) * 256;
        float4 z = make_float4(0.f, 0.f, 0.f, 0.f);
        float4* agg4 = (float4*)g_agg;
        for (size_t idx = i; idx < total4; idx += stride) agg4[idx] = z;
    }
}

// ---------------- kernel 2: scatter + ea copy + ei copy + colsum -------------
__device__ __forceinline__ void load8_idx(const int* __restrict__ recv,
                                          int e, int r[8]) {
    int4 a = __ldcs((const int4*)(recv + e));
    int4 b = __ldcs((const int4*)(recv + e + 4));
    r[0] = a.x; r[1] = a.y; r[2] = a.z; r[3] = a.w;
    r[4] = b.x; r[5] = b.y; r[6] = b.z; r[7] = b.w;
}
__device__ __forceinline__ void load8_idx(const long long* __restrict__ recv,
                                          int e, int r[8]) {
    #pragma unroll
    for (int i = 0; i < 8; i++) r[i] = (int)__ldcs(&recv[e + i]);
}

template<typename IDX>
__global__ void __launch_bounds__(256, 4)
scatter_copy_kernel(const float4* __restrict__ ea,
                    const IDX* __restrict__ recv,
                    float4* __restrict__ out_ea,
                    const IDX* __restrict__ ei,
                    float* __restrict__ out_ei_f,
                    long long* __restrict__ out_ei_raw,
                    int n_ei,
                    int n_edges) {
    int tid  = blockIdx.x * blockDim.x + threadIdx.x;
    int nT   = gridDim.x * blockDim.x;

    if (out_ei_f) {
        for (int i = tid; i < n_ei; i += nT)
            __stcs(&out_ei_f[i], (float)__ldcs(&((const int*)ei)[i]));
    } else if (out_ei_raw) {
        for (int i = tid; i < n_ei; i += nT)
            __stcs(&out_ei_raw[i], __ldcs(&((const long long*)ei)[i]));
    }

    int wl   = threadIdx.x >> 5;
    int lane = threadIdx.x & 31;
    int gw   = blockIdx.x * 8 + wl;
    int nW   = gridDim.x * 8;

    float4 acc = make_float4(0.f, 0.f, 0.f, 0.f);

    int e8 = n_edges & ~7;
    for (int e = gw * 8; e + 7 < e8; e += nW * 8) {
        int r[8];
        load8_idx(recv, e, r);
        float4 v[8];
        #pragma unroll
        for (int i = 0; i < 8; i++)
            v[i] = __ldcs(&ea[(size_t)(e + i) * 32 + lane]);
        if (out_ea) {
            #pragma unroll
            for (int i = 0; i < 8; i++)
                __stcs(&out_ea[(size_t)(e + i) * 32 + lane], v[i]);
        }
        #pragma unroll
        for (int i = 0; i < 8; i++) {
            acc.x += v[i].x; acc.y += v[i].y;
            acc.z += v[i].z; acc.w += v[i].w;
        }
        #pragma unroll
        for (int i = 0; i < 8; i++) {
            float* d = g_agg + (size_t)r[i] * HIDDEN + lane * 4;
            asm volatile("red.global.add.v4.f32 [%0], {%1,%2,%3,%4};"
                         :: "l"(d), "f"(v[i].x), "f"(v[i].y),
                            "f"(v[i].z), "f"(v[i].w) : "memory");
        }
    }
    for (int e = e8 + gw; e < n_edges; e += nW) {
        int r = (int)__ldcs(&recv[e]);
        float4 v = __ldcs(&ea[(size_t)e * 32 + lane]);
        if (out_ea) __stcs(&out_ea[(size_t)e * 32 + lane], v);
        acc.x += v.x; acc.y += v.y; acc.z += v.z; acc.w += v.w;
        float* dst = g_agg + (size_t)r * HIDDEN + lane * 4;
        asm volatile("red.global.add.v4.f32 [%0], {%1,%2,%3,%4};"
                     :: "l"(dst), "f"(v.x), "f"(v.y), "f"(v.z), "f"(v.w)
                     : "memory");
    }

    __shared__ float4 reds[8][32];
    reds[wl][lane] = acc;
    __syncthreads();
    if (wl == 0) {
        float4 s = reds[0][lane];
        #pragma unroll
        for (int w = 1; w < 8; w++) {
            float4 t = reds[w][lane];
            s.x += t.x; s.y += t.y; s.z += t.z; s.w += t.w;
        }
        atomicAdd(&g_colsum[lane * 4 + 0], s.x);
        atomicAdd(&g_colsum[lane * 4 + 1], s.y);
        atomicAdd(&g_colsum[lane * 4 + 2], s.z);
        atomicAdd(&g_colsum[lane * 4 + 3], s.w);
    }
}

// ---------------- kernel 3: fold mean into bias (parallel) -------------------
__global__ void b1eff_kernel(const float* __restrict__ W1,
                             const float* __restrict__ b1, int n_nodes) {
    int j = blockIdx.x;
    int k = threadIdx.x;
    float inv = 1.0f / (float)n_nodes;
    float v = g_colsum[k] * inv * __ldg(&W1[(size_t)(HIDDEN + k) * HIDDEN + j]);
    #pragma unroll
    for (int o = 16; o > 0; o >>= 1) v += __shfl_down_sync(0xffffffffu, v, o);
    __shared__ float red[4];
    if ((k & 31) == 0) red[k >> 5] = v;
    __syncthreads();
    if (k == 0)
        g_b1eff[j] = b1[j] - (red[0] + red[1] + red[2] + red[3]);
}

// ---------------- fused 2-layer tf32 MLP: 64-row tiles, 2 blocks/SM ----------
// 512 threads = 16 warps (4 M x 4 N), warp tile 16x32, block tile 64x128.
// SPAD=33 (conflict-free: banks = lg + 8q mod 32). Arena 50.5 KB -> 2 blocks/SM
// co-resident (8 warps/SMSP) hide the LDS->MMA latency chains.
// Arena (words):
//   [0, 4*2112)       : Hs[0..3] (phase1 aliases: As = +0, Bs = +2112)
//   [8448, 12672)     : Bs2
//   [12672, +256)     : bias1, bias2
#define SPAD 33
#define HT_W 2112            // 64 * 33
#define BT_W 4224            // 128 * 33
#define ARENA_WORDS (4 * HT_W + BT_W + 256)

__global__ void __launch_bounds__(512, 2)
fused_mlp_kernel(const float* __restrict__ A0,
                 const float* __restrict__ A1,
                 const float* __restrict__ b2,
                 float* __restrict__ out, int n_rows) {
    extern __shared__ uint32_t sm[];
    uint32_t* As  = sm;                  // 2112 words
    uint32_t* Bs  = sm + HT_W;           // 4224 words (overlays Hs[1..2])
    uint32_t* Bs2 = sm + 4 * HT_W;
    float*    sB1 = (float*)(sm + 4 * HT_W + BT_W);
    float*    sB2 = (float*)(sm + 4 * HT_W + BT_W + 128);

    int tid  = threadIdx.x;            // 0..511
    int lane = tid & 31;
    int wid  = tid >> 5;               // 0..15
    int q    = lane & 3;
    int lg   = lane >> 2;
    int wm   = wid >> 2;               // 0..3 : 16 rows each
    int wn   = wid & 3;                // 0..3 : 32 cols each
    int Rw   = wm * 16;
    int Nw   = wn * 32;
    int row0 = blockIdx.x * 64;

    if (tid < HIDDEN) {
        sB1[tid] = g_b1eff[tid];
        sB2[tid] = b2[tid];
    }

    float c1[4][4];
    #pragma unroll
    for (int j = 0; j < 4; j++)
        #pragma unroll
        for (int t = 0; t < 4; t++) c1[j][t] = 0.0f;

    float4 ar;          // A prefetch (1 float4/thread: 64 rows x 8 f4)
    uint4  br[2];       // B prefetch (1024 uint4 / 512 thr)

    auto ldA = [&](int t) {
        const float* Asrc = (t >= 4) ? A1 : A0;
        int kb = (t & 3) * 32;
        int row = tid >> 3, tt = tid & 7;
        int grow = row0 + row;
        ar = (grow < n_rows)
            ? __ldg((const float4*)&Asrc[(size_t)grow * HIDDEN + kb + tt * 4])
            : make_float4(0.f, 0.f, 0.f, 0.f);
    };
    auto ldB1 = [&](int t) {
        const uint4* src = (const uint4*)&g_W1t[t * 4096];
        br[0] = __ldg(&src[tid]);
        br[1] = __ldg(&src[512 + tid]);
    };
    auto stA = [&]() {
        int row = tid >> 3, tt = tid & 7;
        uint32_t* dst = &As[row * SPAD + tt];
        dst[0]  = f2tf32(ar.x);
        dst[8]  = f2tf32(ar.y);
        dst[16] = f2tf32(ar.z);
        dst[24] = f2tf32(ar.w);
    };
    auto stB = [&](uint32_t* buf) {
        #pragma unroll
        for (int j = 0; j < 2; j++) {
            int o  = (j * 512 + tid) * 4;
            int n  = o >> 5;
            int pk = o & 31;
            uint32_t* dst = &buf[n * SPAD + pk];
            dst[0] = br[j].x; dst[1] = br[j].y;
            dst[2] = br[j].z; dst[3] = br[j].w;
        }
    };

    // ---------------- phase 1: c1 = [A0|A1] @ W1 -----------------------------
    ldA(0); ldB1(0);
    for (int t = 0; t < 8; t++) {
        stA();
        stB(Bs);
        __syncthreads();
        if (t < 7) { ldA(t + 1); ldB1(t + 1); }

        #pragma unroll
        for (int s = 0; s < 4; s++) {
            uint32_t a[4];
            int r = Rw + lg;
            int o0 = r * SPAD + q * 8 + 2 * s;
            int o1 = (r + 8) * SPAD + q * 8 + 2 * s;
            a[0] = As[o0]; a[2] = As[o0 + 1];
            a[1] = As[o1]; a[3] = As[o1 + 1];
            uint32_t b[4][2];
            #pragma unroll
            for (int nt = 0; nt < 4; nt++) {
                int ob = (Nw + nt * 8 + lg) * SPAD + q * 8 + 2 * s;
                b[nt][0] = Bs[ob]; b[nt][1] = Bs[ob + 1];
            }
            #pragma unroll
            for (int nt = 0; nt < 4; nt++)
                asm volatile(
                    "mma.sync.aligned.m16n8k8.row.col.f32.tf32.tf32.f32 "
                    "{%0,%1,%2,%3}, {%4,%5,%6,%7}, {%8,%9}, {%0,%1,%2,%3};"
                    : "+f"(c1[nt][0]), "+f"(c1[nt][1]),
                      "+f"(c1[nt][2]), "+f"(c1[nt][3])
                    : "r"(a[0]), "r"(a[1]), "r"(a[2]), "r"(a[3]),
                      "r"(b[nt][0]), "r"(b[nt][1]));
        }
        __syncthreads();
    }

    // ---------------- phase 2: stage h into Hs[0..3], x = h @ W2 + b2 --------
    {
        int r0 = Rw + lg;
        int r1 = r0 + 8;
        #pragma unroll
        for (int nt = 0; nt < 4; nt++) {
            int col = Nw + nt * 8 + 2 * q;
            int lk0 = nt * 8 + 2 * q;
            float bb0 = sB1[col], bb1 = sB1[col + 1];
            float v0 = fmaxf(c1[nt][0] + bb0, 0.f);
            float v1 = fmaxf(c1[nt][1] + bb1, 0.f);
            float v2 = fmaxf(c1[nt][2] + bb0, 0.f);
            float v3 = fmaxf(c1[nt][3] + bb1, 0.f);
            int p0 = (lk0 & 3) * 8 + (lk0 >> 2);
            int p1 = ((lk0 + 1) & 3) * 8 + ((lk0 + 1) >> 2);
            uint32_t* hb = &sm[wn * HT_W];
            hb[r0 * SPAD + p0] = f2tf32(v0);
            hb[r0 * SPAD + p1] = f2tf32(v1);
            hb[r1 * SPAD + p0] = f2tf32(v2);
            hb[r1 * SPAD + p1] = f2tf32(v3);
        }
    }

    float c2[4][4];
    #pragma unroll
    for (int j = 0; j < 4; j++)
        #pragma unroll
        for (int t = 0; t < 4; t++) c2[j][t] = 0.0f;

    auto ldB2 = [&](int t) {
        const uint4* src = (const uint4*)&g_W2t[t * 4096];
        br[0] = __ldg(&src[tid]);
        br[1] = __ldg(&src[512 + tid]);
    };

    ldB2(0);
    for (int s = 0; s < 4; s++) {
        stB(Bs2);
        __syncthreads();           // covers h staging (s==0) + Bs2 fill
        if (s < 3) ldB2(s + 1);

        const uint32_t* Hb = sm + s * HT_W;
        #pragma unroll
        for (int ss = 0; ss < 4; ss++) {
            uint32_t a[4];
            int r = Rw + lg;
            int o0 = r * SPAD + q * 8 + 2 * ss;
            int o1 = (r + 8) * SPAD + q * 8 + 2 * ss;
            a[0] = Hb[o0]; a[2] = Hb[o0 + 1];
            a[1] = Hb[o1]; a[3] = Hb[o1 + 1];
            uint32_t b[4][2];
            #pragma unroll
            for (int nt = 0; nt < 4; nt++) {
                int ob = (Nw + nt * 8 + lg) * SPAD + q * 8 + 2 * ss;
                b[nt][0] = Bs2[ob]; b[nt][1] = Bs2[ob + 1];
            }
            #pragma unroll
            for (int nt = 0; nt < 4; nt++)
                asm volatile(
                    "mma.sync.aligned.m16n8k8.row.col.f32.tf32.tf32.f32 "
                    "{%0,%1,%2,%3}, {%4,%5,%6,%7}, {%8,%9}, {%0,%1,%2,%3};"
                    : "+f"(c2[nt][0]), "+f"(c2[nt][1]),
                      "+f"(c2[nt][2]), "+f"(c2[nt][3])
                    : "r"(a[0]), "r"(a[1]), "r"(a[2]), "r"(a[3]),
                      "r"(b[nt][0]), "r"(b[nt][1]));
        }
        __syncthreads();
    }

    // epilogue
    {
        int r0g = row0 + Rw + lg;
        int r1g = r0g + 8;
        #pragma unroll
        for (int nt = 0; nt < 4; nt++) {
            int col = Nw + nt * 8 + 2 * q;
            float bb0 = sB2[col], bb1 = sB2[col + 1];
            if (r0g < n_rows)
                *(float2*)&out[(size_t)r0g * HIDDEN + col] =
                    make_float2(c2[nt][0] + bb0, c2[nt][1] + bb1);
            if (r1g < n_rows)
                *(float2*)&out[(size_t)r1g * HIDDEN + col] =
                    make_float2(c2[nt][2] + bb0, c2[nt][3] + bb1);
        }
    }
}

// ---------------- launcher ---------------------------------------------------
extern "C" void kernel_launch(void* const* d_in, const int* in_sizes, int n_in,
                              void* d_out, int out_size) {
    const float* node_attr  = (const float*)d_in[0];
    const void*  edge_index = d_in[1];
    const float* edge_attr  = (const float*)d_in[2];
    const float* W1         = (const float*)d_in[3];
    const float* b1         = (const float*)d_in[4];
    const float* W2         = (const float*)d_in[5];
    const float* b2         = (const float*)d_in[6];

    int n_nodes = in_sizes[0] / HIDDEN;
    int n_edges = in_sizes[1] / 2;

    size_t x_el  = (size_t)n_nodes * HIDDEN;
    size_t ei_el = 2 * (size_t)n_edges;
    size_t ea_el = (size_t)n_edges * HIDDEN;

    float* out   = (float*)d_out;
    float* out_x = out;

    size_t os = (size_t)out_size;
    bool idx64 = false;
    float*     out_ei_f   = nullptr;
    long long* out_ei_raw = nullptr;
    float*     out_ea     = nullptr;
    if (os == x_el + ei_el + ea_el) {
        idx64 = false;
        out_ei_f = out + x_el;
        out_ea   = out + x_el + ei_el;
    } else if (os == x_el + 2 * ei_el + ea_el) {
        idx64 = true;
        out_ei_raw = (long long*)(out + x_el);
        out_ea     = out + x_el + 2 * ei_el;
    }

    float* d_agg; cudaGetSymbolAddress((void**)&d_agg, g_agg);

    // 1. fused init: wconv (blocks 0-11) + zero agg (blocks 12+)
    init_kernel<<<2060, 256>>>(W1, W2, n_nodes);

    // 2. scatter + ea copy + ei copy + colsum
    {
        int blocks = 1184;
        int n_ei = 2 * n_edges;
        if (idx64) {
            const long long* eil = (const long long*)edge_index;
            scatter_copy_kernel<long long><<<blocks, 256>>>(
                (const float4*)edge_attr, eil + n_edges, (float4*)out_ea,
                eil, nullptr, out_ei_raw, n_ei, n_edges);
        } else {
            const int* eii = (const int*)edge_index;
            scatter_copy_kernel<int><<<blocks, 256>>>(
                (const float4*)edge_attr, eii + n_edges, (float4*)out_ea,
                eii, out_ei_f, nullptr, n_ei, n_edges);
        }
    }

    // 3. fold column means into bias
    b1eff_kernel<<<HIDDEN, HIDDEN>>>(W1, b1, n_nodes);

    // 4. fused MLP (64-row tiles, 2 blocks/SM)
    {
        int smem_bytes = ARENA_WORDS * 4;
        cudaFuncSetAttribute(fused_mlp_kernel,
                             cudaFuncAttributeMaxDynamicSharedMemorySize,
                             smem_bytes);
        int blocks = (n_nodes + 63) / 64;
        fused_mlp_kernel<<<blocks, 512, smem_bytes>>>(node_attr, d_agg, b2,
                                                      out_x, n_nodes);
    }
}

// round 15
// speedup vs baseline: 1.1799x; 1.1799x over previous
#include <cuda_runtime.h>
#include <cuda_bf16.h>
#include <cuda_fp16.h>
#include <cstdint>

#define HIDDEN 128
#define MAX_NODES 50048
#define MAX_EDGES 800000

// ---------------- scratch (static device globals; no allocation) -------------
__device__ float    g_agg[(size_t)MAX_NODES * HIDDEN];
__device__ float    g_colsum[HIDDEN];
__device__ float    g_b1eff[HIDDEN];
__device__ uint32_t g_W1t[4 * 4096];   // W1 f16x2 pairs, 4 k-macro-tiles (64k ea)
__device__ uint32_t g_W2t[2 * 4096];   // W2 f16x2 pairs, 2 k-macro-tiles

__device__ __forceinline__ uint32_t pack_h2(float a, float b) {
    __half2 h = __floats2half2_rn(a, b);
    return *(uint32_t*)&h;
}

// ---------------- kernel 1: fused init (zero agg+colsum, wconv W1/W2) --------
// blocks [0,6): weight macro-tiles (4 W1 + 2 W2). blocks [6,...): zero agg.
// pair j of macro-tile t covers k = t*64 + 2j, +1 ; stored at n*32 + p(j),
// p(j) = (j&3)*8 + (j>>2), inverse j = (pk&7)*4 + (pk>>3).
__global__ void __launch_bounds__(256)
init_kernel(const float* __restrict__ W1, const float* __restrict__ W2,
            int n_nodes) {
    int b   = blockIdx.x;
    int tid = threadIdx.x;
    if (b < 6) {
        const float* W = (b < 4) ? W1 : W2;
        uint32_t*    o = (b < 4) ? g_W1t : g_W2t;
        int t = (b < 4) ? b : b - 4;
        #pragma unroll
        for (int j = 0; j < 16; j++) {
            int oo = j * 256 + tid;        // 0..4095
            int n  = oo >> 5;
            int pk = oo & 31;
            int jp = (pk & 7) * 4 + (pk >> 3);
            int k0 = t * 64 + 2 * jp;
            o[t * 4096 + oo] = pack_h2(__ldg(&W[(size_t)k0 * HIDDEN + n]),
                                       __ldg(&W[(size_t)(k0 + 1) * HIDDEN + n]));
        }
        if (b == 0 && tid < HIDDEN) g_colsum[tid] = 0.0f;
    } else {
        size_t total4 = (size_t)n_nodes * (HIDDEN / 4);
        size_t i      = (size_t)(b - 6) * 256 + tid;
        size_t stride = (size_t)(gridDim.x - 6) * 256;
        float4 z = make_float4(0.f, 0.f, 0.f, 0.f);
        float4* agg4 = (float4*)g_agg;
        for (size_t idx = i; idx < total4; idx += stride) agg4[idx] = z;
    }
}

// ---------------- kernel 2: scatter + ea copy + ei copy + colsum -------------
__device__ __forceinline__ void load8_idx(const int* __restrict__ recv,
                                          int e, int r[8]) {
    int4 a = __ldcs((const int4*)(recv + e));
    int4 b = __ldcs((const int4*)(recv + e + 4));
    r[0] = a.x; r[1] = a.y; r[2] = a.z; r[3] = a.w;
    r[4] = b.x; r[5] = b.y; r[6] = b.z; r[7] = b.w;
}
__device__ __forceinline__ void load8_idx(const long long* __restrict__ recv,
                                          int e, int r[8]) {
    #pragma unroll
    for (int i = 0; i < 8; i++) r[i] = (int)__ldcs(&recv[e + i]);
}

template<typename IDX>
__global__ void __launch_bounds__(256, 4)
scatter_copy_kernel(const float4* __restrict__ ea,
                    const IDX* __restrict__ recv,
                    float4* __restrict__ out_ea,
                    const IDX* __restrict__ ei,
                    float* __restrict__ out_ei_f,
                    long long* __restrict__ out_ei_raw,
                    int n_ei,
                    int n_edges) {
    int tid  = blockIdx.x * blockDim.x + threadIdx.x;
    int nT   = gridDim.x * blockDim.x;

    if (out_ei_f) {
        for (int i = tid; i < n_ei; i += nT)
            __stcs(&out_ei_f[i], (float)__ldcs(&((const int*)ei)[i]));
    } else if (out_ei_raw) {
        for (int i = tid; i < n_ei; i += nT)
            __stcs(&out_ei_raw[i], __ldcs(&((const long long*)ei)[i]));
    }

    int wl   = threadIdx.x >> 5;
    int lane = threadIdx.x & 31;
    int gw   = blockIdx.x * 8 + wl;
    int nW   = gridDim.x * 8;

    float4 acc = make_float4(0.f, 0.f, 0.f, 0.f);

    int e8 = n_edges & ~7;
    for (int e = gw * 8; e + 7 < e8; e += nW * 8) {
        int r[8];
        load8_idx(recv, e, r);
        float4 v[8];
        #pragma unroll
        for (int i = 0; i < 8; i++)
            v[i] = __ldcs(&ea[(size_t)(e + i) * 32 + lane]);
        if (out_ea) {
            #pragma unroll
            for (int i = 0; i < 8; i++)
                __stcs(&out_ea[(size_t)(e + i) * 32 + lane], v[i]);
        }
        #pragma unroll
        for (int i = 0; i < 8; i++) {
            acc.x += v[i].x; acc.y += v[i].y;
            acc.z += v[i].z; acc.w += v[i].w;
        }
        #pragma unroll
        for (int i = 0; i < 8; i++) {
            float* d = g_agg + (size_t)r[i] * HIDDEN + lane * 4;
            asm volatile("red.global.add.v4.f32 [%0], {%1,%2,%3,%4};"
                         :: "l"(d), "f"(v[i].x), "f"(v[i].y),
                            "f"(v[i].z), "f"(v[i].w) : "memory");
        }
    }
    for (int e = e8 + gw; e < n_edges; e += nW) {
        int r = (int)__ldcs(&recv[e]);
        float4 v = __ldcs(&ea[(size_t)e * 32 + lane]);
        if (out_ea) __stcs(&out_ea[(size_t)e * 32 + lane], v);
        acc.x += v.x; acc.y += v.y; acc.z += v.z; acc.w += v.w;
        float* dst = g_agg + (size_t)r * HIDDEN + lane * 4;
        asm volatile("red.global.add.v4.f32 [%0], {%1,%2,%3,%4};"
                     :: "l"(dst), "f"(v.x), "f"(v.y), "f"(v.z), "f"(v.w)
                     : "memory");
    }

    __shared__ float4 reds[8][32];
    reds[wl][lane] = acc;
    __syncthreads();
    if (wl == 0) {
        float4 s = reds[0][lane];
        #pragma unroll
        for (int w = 1; w < 8; w++) {
            float4 t = reds[w][lane];
            s.x += t.x; s.y += t.y; s.z += t.z; s.w += t.w;
        }
        atomicAdd(&g_colsum[lane * 4 + 0], s.x);
        atomicAdd(&g_colsum[lane * 4 + 1], s.y);
        atomicAdd(&g_colsum[lane * 4 + 2], s.z);
        atomicAdd(&g_colsum[lane * 4 + 3], s.w);
    }
}

// ---------------- kernel 3: fold mean into bias (parallel) -------------------
__global__ void b1eff_kernel(const float* __restrict__ W1,
                             const float* __restrict__ b1, int n_nodes) {
    int j = blockIdx.x;
    int k = threadIdx.x;
    float inv = 1.0f / (float)n_nodes;
    float v = g_colsum[k] * inv * __ldg(&W1[(size_t)(HIDDEN + k) * HIDDEN + j]);
    #pragma unroll
    for (int o = 16; o > 0; o >>= 1) v += __shfl_down_sync(0xffffffffu, v, o);
    __shared__ float red[4];
    if ((k & 31) == 0) red[k >> 5] = v;
    __syncthreads();
    if (k == 0)
        g_b1eff[j] = b1[j] - (red[0] + red[1] + red[2] + red[3]);
}

// ---------------- fused 2-layer FP16 MMA MLP ---------------------------------
// 512 thr = 16 warps (2 M x 4 N... wm 0..1 / wn 0..3 x 2 wm groups? -> as
// round-12: wm = wid>>2 (0..3? no)). Round-12 mapping: wm = wid>>2 in 0..3 was
// for 4 M groups; here we keep round-12's 128x128 block tile with 16 warps:
// wm 0..3 x wn 0..3, warp tile 32x32, mt 0..1.
// Element = f16x2 pair. k-macro-tile = 64 (32 pairs/row, SPAD=37).
// mma.sync.m16n8k16.f16: per s-step (K=16) lane reads pairs 8s+q, 8s+q+4
// -> stored contiguously at q*8+2s (+1): identical indexing to tf32 version.
// Arena (words): Hs0 = sm[0,4736), Hs1 = sm[4736,9472) (phase1: As, Bs),
// Bs2 = sm[9472,14208), biases at 14208.
#define SPAD 37
#define HS_W 4736
#define ARENA_WORDS (3 * HS_W + 256)

__global__ void __launch_bounds__(512)
fused_mlp_kernel(const float* __restrict__ A0,
                 const float* __restrict__ A1,
                 const float* __restrict__ b2,
                 float* __restrict__ out, int n_rows) {
    extern __shared__ uint32_t sm[];
    uint32_t* As  = sm;
    uint32_t* Bs  = sm + HS_W;
    uint32_t* Bs2 = sm + 2 * HS_W;
    float*    sB1 = (float*)(sm + 3 * HS_W);
    float*    sB2 = (float*)(sm + 3 * HS_W + 128);

    int tid  = threadIdx.x;            // 0..511
    int lane = tid & 31;
    int wid  = tid >> 5;               // 0..15
    int q    = lane & 3;
    int lg   = lane >> 2;
    int wm   = wid >> 2;               // 0..3 : 32 rows each
    int wn   = wid & 3;                // 0..3 : 32 cols each
    int Rw   = wm * 32;
    int Nw   = wn * 32;
    int row0 = blockIdx.x * 128;

    if (tid < HIDDEN) {
        sB1[tid] = g_b1eff[tid];
        sB2[tid] = b2[tid];
    }

    float c1[2][4][4];
    #pragma unroll
    for (int i = 0; i < 2; i++)
        #pragma unroll
        for (int j = 0; j < 4; j++)
            #pragma unroll
            for (int t = 0; t < 4; t++) c1[i][j][t] = 0.0f;

    float4 ar[4];      // A prefetch: 128 rows x 16 f4 = 2048 f4 / 512 thr
    uint4  br[2];      // B prefetch: 4096 words = 1024 u4 / 512 thr

    auto ldA = [&](int t) {            // macro-tile t (64 k)
        const float* Asrc = (t >= 2) ? A1 : A0;
        int kb = (t & 1) * 64;
        #pragma unroll
        for (int it = 0; it < 4; it++) {
            int idx = tid + it * 512;  // 0..2047
            int row = idx >> 4, f = idx & 15;
            int grow = row0 + row;
            ar[it] = (grow < n_rows)
                ? __ldg((const float4*)&Asrc[(size_t)grow * HIDDEN + kb + f * 4])
                : make_float4(0.f, 0.f, 0.f, 0.f);
        }
    };
    auto ldB1 = [&](int t) {
        const uint4* src = (const uint4*)&g_W1t[t * 4096];
        br[0] = __ldg(&src[tid]);
        br[1] = __ldg(&src[512 + tid]);
    };
    auto stA = [&]() {
        #pragma unroll
        for (int it = 0; it < 4; it++) {
            int idx = tid + it * 512;
            int row = idx >> 4, f = idx & 15;
            int p0 = (f & 1) * 16 + (f >> 1);   // p(2f)
            uint32_t* dst = &As[row * SPAD + p0];
            dst[0] = pack_h2(ar[it].x, ar[it].y);   // pair 2f
            dst[8] = pack_h2(ar[it].z, ar[it].w);   // pair 2f+1 at p0+8
        }
    };
    auto stB = [&](uint32_t* buf) {
        #pragma unroll
        for (int j = 0; j < 2; j++) {
            int o  = (j * 512 + tid) * 4;
            int n  = o >> 5;
            int pk = o & 31;
            uint32_t* dst = &buf[n * SPAD + pk];
            dst[0] = br[j].x; dst[1] = br[j].y;
            dst[2] = br[j].z; dst[3] = br[j].w;
        }
    };

    // ---------------- phase 1: c1 = [A0|A1] @ W1 (4 macro-tiles) -------------
    ldA(0); ldB1(0);
    for (int t = 0; t < 4; t++) {
        stA();
        stB(Bs);
        __syncthreads();
        if (t < 3) { ldA(t + 1); ldB1(t + 1); }

        #pragma unroll
        for (int s = 0; s < 4; s++) {          // 4 K=16 steps per macro-tile
            uint32_t a[2][4];
            #pragma unroll
            for (int mt = 0; mt < 2; mt++) {
                int r = Rw + mt * 16 + lg;
                int o0 = r * SPAD + q * 8 + 2 * s;
                int o1 = (r + 8) * SPAD + q * 8 + 2 * s;
                a[mt][0] = As[o0]; a[mt][2] = As[o0 + 1];
                a[mt][1] = As[o1]; a[mt][3] = As[o1 + 1];
            }
            uint32_t b[4][2];
            #pragma unroll
            for (int nt = 0; nt < 4; nt++) {
                int ob = (Nw + nt * 8 + lg) * SPAD + q * 8 + 2 * s;
                b[nt][0] = Bs[ob]; b[nt][1] = Bs[ob + 1];
            }
            #pragma unroll
            for (int mt = 0; mt < 2; mt++)
                #pragma unroll
                for (int nt = 0; nt < 4; nt++)
                    asm volatile(
                        "mma.sync.aligned.m16n8k16.row.col.f32.f16.f16.f32 "
                        "{%0,%1,%2,%3}, {%4,%5,%6,%7}, {%8,%9}, {%0,%1,%2,%3};"
                        : "+f"(c1[mt][nt][0]), "+f"(c1[mt][nt][1]),
                          "+f"(c1[mt][nt][2]), "+f"(c1[mt][nt][3])
                        : "r"(a[mt][0]), "r"(a[mt][1]),
                          "r"(a[mt][2]), "r"(a[mt][3]),
                          "r"(b[nt][0]), "r"(b[nt][1]));
        }
        __syncthreads();
    }

    // ---------------- phase 2: stage h (f16x2) then x = h @ W2 + b2 ----------
    #pragma unroll
    for (int mt = 0; mt < 2; mt++) {
        int r0 = Rw + mt * 16 + lg;
        int r1 = r0 + 8;
        #pragma unroll
        for (int nt = 0; nt < 4; nt++) {
            int col = Nw + nt * 8 + 2 * q;     // even
            float bb0 = sB1[col], bb1 = sB1[col + 1];
            float v0 = fmaxf(c1[mt][nt][0] + bb0, 0.f);
            float v1 = fmaxf(c1[mt][nt][1] + bb1, 0.f);
            float v2 = fmaxf(c1[mt][nt][2] + bb0, 0.f);
            float v3 = fmaxf(c1[mt][nt][3] + bb1, 0.f);
            int macro = col >> 6;
            int jh = (col >> 1) & 31;
            int pk = (jh & 3) * 8 + (jh >> 2);
            uint32_t* hb = &sm[macro * HS_W];
            hb[r0 * SPAD + pk] = pack_h2(v0, v1);
            hb[r1 * SPAD + pk] = pack_h2(v2, v3);
        }
    }

    float c2[2][4][4];
    #pragma unroll
    for (int i = 0; i < 2; i++)
        #pragma unroll
        for (int j = 0; j < 4; j++)
            #pragma unroll
            for (int t = 0; t < 4; t++) c2[i][j][t] = 0.0f;

    auto ldB2 = [&](int t) {
        const uint4* src = (const uint4*)&g_W2t[t * 4096];
        br[0] = __ldg(&src[tid]);
        br[1] = __ldg(&src[512 + tid]);
    };

    ldB2(0);
    for (int s = 0; s < 2; s++) {              // 2 macro-tiles of K=64
        stB(Bs2);
        __syncthreads();                       // covers h staging at s==0
        if (s < 1) ldB2(1);

        const uint32_t* Hb = sm + s * HS_W;
        #pragma unroll
        for (int ss = 0; ss < 4; ss++) {
            uint32_t a[2][4];
            #pragma unroll
            for (int mt = 0; mt < 2; mt++) {
                int r = Rw + mt * 16 + lg;
                int o0 = r * SPAD + q * 8 + 2 * ss;
                int o1 = (r + 8) * SPAD + q * 8 + 2 * ss;
                a[mt][0] = Hb[o0]; a[mt][2] = Hb[o0 + 1];
                a[mt][1] = Hb[o1]; a[mt][3] = Hb[o1 + 1];
            }
            uint32_t b[4][2];
            #pragma unroll
            for (int nt = 0; nt < 4; nt++) {
                int ob = (Nw + nt * 8 + lg) * SPAD + q * 8 + 2 * ss;
                b[nt][0] = Bs2[ob]; b[nt][1] = Bs2[ob + 1];
            }
            #pragma unroll
            for (int mt = 0; mt < 2; mt++)
                #pragma unroll
                for (int nt = 0; nt < 4; nt++)
                    asm volatile(
                        "mma.sync.aligned.m16n8k16.row.col.f32.f16.f16.f32 "
                        "{%0,%1,%2,%3}, {%4,%5,%6,%7}, {%8,%9}, {%0,%1,%2,%3};"
                        : "+f"(c2[mt][nt][0]), "+f"(c2[mt][nt][1]),
                          "+f"(c2[mt][nt][2]), "+f"(c2[mt][nt][3])
                        : "r"(a[mt][0]), "r"(a[mt][1]),
                          "r"(a[mt][2]), "r"(a[mt][3]),
                          "r"(b[nt][0]), "r"(b[nt][1]));
        }
        __syncthreads();
    }

    // epilogue
    #pragma unroll
    for (int mt = 0; mt < 2; mt++) {
        int r0g = row0 + Rw + mt * 16 + lg;
        int r1g = r0g + 8;
        #pragma unroll
        for (int nt = 0; nt < 4; nt++) {
            int col = Nw + nt * 8 + 2 * q;
            float bb0 = sB2[col], bb1 = sB2[col + 1];
            if (r0g < n_rows)
                *(float2*)&out[(size_t)r0g * HIDDEN + col] =
                    make_float2(c2[mt][nt][0] + bb0, c2[mt][nt][1] + bb1);
            if (r1g < n_rows)
                *(float2*)&out[(size_t)r1g * HIDDEN + col] =
                    make_float2(c2[mt][nt][2] + bb0, c2[mt][nt][3] + bb1);
        }
    }
}

// ---------------- launcher ---------------------------------------------------
extern "C" void kernel_launch(void* const* d_in, const int* in_sizes, int n_in,
                              void* d_out, int out_size) {
    const float* node_attr  = (const float*)d_in[0];
    const void*  edge_index = d_in[1];
    const float* edge_attr  = (const float*)d_in[2];
    const float* W1         = (const float*)d_in[3];
    const float* b1         = (const float*)d_in[4];
    const float* W2         = (const float*)d_in[5];
    const float* b2         = (const float*)d_in[6];

    int n_nodes = in_sizes[0] / HIDDEN;
    int n_edges = in_sizes[1] / 2;

    size_t x_el  = (size_t)n_nodes * HIDDEN;
    size_t ei_el = 2 * (size_t)n_edges;
    size_t ea_el = (size_t)n_edges * HIDDEN;

    float* out   = (float*)d_out;
    float* out_x = out;

    size_t os = (size_t)out_size;
    bool idx64 = false;
    float*     out_ei_f   = nullptr;
    long long* out_ei_raw = nullptr;
    float*     out_ea     = nullptr;
    if (os == x_el + ei_el + ea_el) {
        idx64 = false;
        out_ei_f = out + x_el;
        out_ea   = out + x_el + ei_el;
    } else if (os == x_el + 2 * ei_el + ea_el) {
        idx64 = true;
        out_ei_raw = (long long*)(out + x_el);
        out_ea     = out + x_el + 2 * ei_el;
    }

    float* d_agg; cudaGetSymbolAddress((void**)&d_agg, g_agg);

    // 1. fused init: wconv (blocks 0-5) + zero agg (blocks 6+)
    init_kernel<<<2054, 256>>>(W1, W2, n_nodes);

    // 2. scatter + ea copy + ei copy + colsum
    {
        int blocks = 1184;
        int n_ei = 2 * n_edges;
        if (idx64) {
            const long long* eil = (const long long*)edge_index;
            scatter_copy_kernel<long long><<<blocks, 256>>>(
                (const float4*)edge_attr, eil + n_edges, (float4*)out_ea,
                eil, nullptr, out_ei_raw, n_ei, n_edges);
        } else {
            const int* eii = (const int*)edge_index;
            scatter_copy_kernel<int><<<blocks, 256>>>(
                (const float4*)edge_attr, eii + n_edges, (float4*)out_ea,
                eii, out_ei_f, nullptr, n_ei, n_edges);
        }
    }

    // 3. fold column means into bias
    b1eff_kernel<<<HIDDEN, HIDDEN>>>(W1, b1, n_nodes);

    // 4. fused MLP (fp16 mma, 512 threads)
    {
        int smem_bytes = ARENA_WORDS * 4;
        cudaFuncSetAttribute(fused_mlp_kernel,
                             cudaFuncAttributeMaxDynamicSharedMemorySize,
                             smem_bytes);
        int blocks = (n_nodes + 127) / 128;
        fused_mlp_kernel<<<blocks, 512, smem_bytes>>>(node_attr, d_agg, b2,
                                                      out_x, n_nodes);
    }
}